// round 6
// baseline (speedup 1.0000x reference)
#include <cuda_runtime.h>

#define BB 256
#define NN 400
#define DD 256
#define DEGC 32
#define EE (BB*NN*DEGC)        // 3276800
#define KK 200
#define NCC (NN-KK)            // 200
#define NT (BB*NN)             // 102400
#define BK (BB*KK)             // 51200
#define BC (BB*NCC)            // 51200
#define EG (NN*DEGC)           // 12800 edges per graph
#define EG4 (EG/4)             // 3200

// output offsets (float32 elements)
#define OFF_DIS   ((size_t)0)
#define OFF_COM   ((size_t)BK*DD)                 // 13107200
#define OFF_PERM  (OFF_COM + (size_t)BC*DD)       // 26214400
#define OFF_PERMC (OFF_PERM + BK)                 // 26265600
#define OFF_SOFT  (OFF_PERMC + BC)                // 26316800
#define OFF_EDIS  (OFF_SOFT + NT)                 // 26419200
#define OFF_ECOM  (OFF_EDIS + EE)                 // 29696000

// Deterministic packed accumulator per node (smem):
//   bits [56:64) : deg_in count
//   bits [0:56)  : sum of (llrint(h * 2^38) + 2^47) per edge
// Integer adds are order-invariant -> bitwise identical every run, and the
// double-precision h + fine scale makes |score error| ~1e-10 (true ordering).
#define AGG_SCALE_D 274877906944.0      // 2^38
#define AGG_BIAS    (1ll << 47)
#define MASK56      ((1ull << 56) - 1ull)

__device__ float  g_score[NT];
__device__ int    g_perm[BK];
__device__ int    g_permc[BC];
__device__ float  g_sumexp_part[BB];

__device__ __forceinline__ unsigned enc_f(float f) {
    unsigned u = __float_as_uint(f);
    return (u >> 31) ? ~u : (u | 0x80000000u);
}

__device__ __forceinline__ unsigned long long pack_edge(double h) {
    long long f = __double2ll_rn(h * AGG_SCALE_D);
    return (1ull << 56) + (unsigned long long)(f + AGG_BIAS);
}

// One block (512 threads) per graph: xw (double), deg_out, aggregation,
// scores, sum-exp partial, bitonic top-k, perm/permc, edge masks.
__global__ void __launch_bounds__(512) k_main(const float* __restrict__ feat,
                                              const float* __restrict__ W,
                                              const float* __restrict__ bptr,
                                              const int* __restrict__ src,
                                              const int* __restrict__ dst,
                                              float* __restrict__ out) {
    __shared__ __align__(16) float sW[DD];
    __shared__ double sh[NN];                // p (double), then h = p*deg^-1/2
    __shared__ int   sdeg[NN];               // deg_out
    __shared__ unsigned long long sacc[NN];  // packed deg_in + agg
    __shared__ float ssc[NN];                // scores (float)
    __shared__ unsigned long long keys[512]; // sort keys; aliased float scratch
    __shared__ int   scn[512];
    __shared__ unsigned char flags[512];

    int g = blockIdx.x;
    int t = threadIdx.x;
    int warp = t >> 5, lane = t & 31;
    int base = g * NN;
    double b0 = (double)bptr[0];

    if (t < DD) sW[t] = W[t];
    if (t < NN) { sdeg[t] = 0; sacc[t] = 0ull; }
    flags[t] = 0;
    __syncthreads();

    // ---- xw: warp-per-node dot in DOUBLE (fixed order => deterministic)
    const float4* w4 = (const float4*)sW;
    for (int node = warp; node < NN; node += 16) {
        const float4* f4 = (const float4*)(feat + (size_t)(base + node) * DD);
        float4 v0 = f4[lane * 2], v1 = f4[lane * 2 + 1];
        float4 w0 = w4[lane * 2], w1 = w4[lane * 2 + 1];
        double acc = 0.0;
        acc += (double)v0.x * (double)w0.x;
        acc += (double)v0.y * (double)w0.y;
        acc += (double)v0.z * (double)w0.z;
        acc += (double)v0.w * (double)w0.w;
        acc += (double)v1.x * (double)w1.x;
        acc += (double)v1.y * (double)w1.y;
        acc += (double)v1.z * (double)w1.z;
        acc += (double)v1.w * (double)w1.w;
#pragma unroll
        for (int o = 16; o > 0; o >>= 1)
            acc += __shfl_down_sync(0xffffffffu, acc, o);
        if (lane == 0) sh[node] = acc;
    }

    const int4* s4 = (const int4*)src + (size_t)g * EG4;
    const int4* d4 = (const int4*)dst + (size_t)g * EG4;

    // ---- deg_out pass (smem int atomics)
    for (int i = t; i < EG4; i += 512) {
        int4 s = s4[i];
        atomicAdd(&sdeg[s.x - base], 1); atomicAdd(&sdeg[s.y - base], 1);
        atomicAdd(&sdeg[s.z - base], 1); atomicAdd(&sdeg[s.w - base], 1);
    }
    __syncthreads();
    if (t < NN) {
        int dgo = sdeg[t]; if (dgo < 1) dgo = 1;
        sh[t] = sh[t] / sqrt((double)dgo);
    }
    __syncthreads();

    // ---- aggregation pass (smem u64 atomics, deterministic)
    for (int i = t; i < EG4; i += 512) {
        int4 s = s4[i];
        int4 d = d4[i];
        atomicAdd(&sacc[d.x - base], pack_edge(sh[s.x - base]));
        atomicAdd(&sacc[d.y - base], pack_edge(sh[s.y - base]));
        atomicAdd(&sacc[d.z - base], pack_edge(sh[s.z - base]));
        atomicAdd(&sacc[d.w - base], pack_edge(sh[s.w - base]));
    }
    __syncthreads();

    // ---- scores (double decode) + sum-exp partial (fixed-order tree)
    float* sred = (float*)keys;
    float ex = 0.f;
    if (t < NN) {
        unsigned long long v = sacc[t];
        unsigned C = (unsigned)(v >> 56);
        long long S = (long long)(v & MASK56);
        double agg = (double)(S - ((long long)C << 47)) * (1.0 / AGG_SCALE_D);
        unsigned Cc = C < 1u ? 1u : C;
        double sd = agg / sqrt((double)Cc) + b0;
        float s = (float)sd;
        ssc[t] = s;
        g_score[base + t] = s;
        ex = expf(s);
    }
    sred[t] = ex;
    __syncthreads();
    for (int o = 256; o > 0; o >>= 1) {
        if (t < o) sred[t] += sred[t + o];
        __syncthreads();
    }
    if (t == 0) g_sumexp_part[g] = sred[0];
    __syncthreads();

    // ---- bitonic sort 512 keys (score desc, idx asc)
    {
        unsigned long long key;
        if (t < NN) {
            unsigned u = enc_f(ssc[t]);
            key = (((unsigned long long)(~u)) << 32) | (unsigned)t;
        } else {
            key = 0xFFFFFFFFFFFFFFFFull;
        }
        keys[t] = key;
    }
    __syncthreads();
    for (int k = 2; k <= 512; k <<= 1) {
        for (int j = k >> 1; j > 0; j >>= 1) {
            int ixj = t ^ j;
            if (ixj > t) {
                bool up = ((t & k) == 0);
                unsigned long long a = keys[t], c = keys[ixj];
                if ((a > c) == up) { keys[t] = c; keys[ixj] = a; }
            }
            __syncthreads();
        }
    }
    if (t < KK) {
        int local = (int)(keys[t] & 0xffffffffu);
        flags[local] = 1;
        int gid = base + local;
        g_perm[g * KK + t] = gid;
        out[OFF_PERM + (size_t)g * KK + t] = (float)gid;
    }
    __syncthreads();
    scn[t] = (t < NN && !flags[t]) ? 1 : 0;
    __syncthreads();
    for (int off = 1; off < 512; off <<= 1) {
        int add = (t >= off) ? scn[t - off] : 0;
        __syncthreads();
        scn[t] += add;
        __syncthreads();
    }
    if (t < NN && !flags[t]) {
        int p = scn[t] - 1;
        int gid = base + t;
        g_permc[g * NCC + p] = gid;
        out[OFF_PERMC + (size_t)g * NCC + p] = (float)gid;
    }
    __syncthreads();

    // ---- edge masks (3rd edge read, L2-hot)
    float4* odis = (float4*)(out + OFF_EDIS) + (size_t)g * EG4;
    float4* ocom = (float4*)(out + OFF_ECOM) + (size_t)g * EG4;
    for (int i = t; i < EG4; i += 512) {
        int4 s = s4[i];
        int4 d = d4[i];
        unsigned char sx = flags[s.x - base], sy = flags[s.y - base];
        unsigned char sz = flags[s.z - base], sw = flags[s.w - base];
        unsigned char dx = flags[d.x - base], dy = flags[d.y - base];
        unsigned char dz = flags[d.z - base], dw = flags[d.w - base];
        float4 dis, com;
        dis.x = (sx & dx) ? 1.f : 0.f;  com.x = (!sx && !dx) ? 1.f : 0.f;
        dis.y = (sy & dy) ? 1.f : 0.f;  com.y = (!sy && !dy) ? 1.f : 0.f;
        dis.z = (sz & dz) ? 1.f : 0.f;  com.z = (!sz && !dz) ? 1.f : 0.f;
        dis.w = (sw & dw) ? 1.f : 0.f;  com.w = (!sw && !dw) ? 1.f : 0.f;
        odis[i] = dis;
        ocom[i] = com;
    }
}

// Gather + softmax. 512 threads = 8 rows x 64 float4-lanes.
// Denominator from 256 per-graph partials in a fixed order (deterministic).
__global__ void __launch_bounds__(512) k_gather(const float* __restrict__ feat,
                                                float* __restrict__ out) {
    __shared__ float ssum;
    int t = threadIdx.x;
    if (t < 32) {
        float a = 0.f;
#pragma unroll
        for (int j = 0; j < 8; j++) a += g_sumexp_part[t * 8 + j];
#pragma unroll
        for (int o = 16; o > 0; o >>= 1) a += __shfl_down_sync(0xffffffffu, a, o);
        if (t == 0) ssum = a;
    }
    __syncthreads();
    float denom = ssum;

    int rowInBlk = t >> 6;
    int lane = t & 63;
    long row = (long)blockIdx.x * 8 + rowInBlk;
    int node; size_t obase;
    if (row < BK) {
        node = g_perm[row];
        obase = OFF_DIS + (size_t)row * DD;
    } else {
        long r2 = row - BK;
        node = g_permc[r2];
        obase = OFF_COM + (size_t)r2 * DD;
    }
    float sc = g_score[node];
    float gate = tanhf(sc);
    const float4* f4 = (const float4*)(feat + (size_t)node * DD);
    float4 v = f4[lane];
    v.x *= gate; v.y *= gate; v.z *= gate; v.w *= gate;
    ((float4*)(out + obase))[lane] = v;
    if (lane == 0) out[OFF_SOFT + node] = expf(sc) / denom;
}

extern "C" void kernel_launch(void* const* d_in, const int* in_sizes, int n_in,
                              void* d_out, int out_size) {
    const float* feat = (const float*)d_in[0];
    const float* W    = (const float*)d_in[1];
    const float* b    = (const float*)d_in[2];
    const int*   src  = (const int*)d_in[3];
    const int*   dst  = (const int*)d_in[4];
    float* out = (float*)d_out;
    (void)in_sizes; (void)n_in; (void)out_size;

    k_main<<<BB, 512>>>(feat, W, b, src, dst, out);
    k_gather<<<NT / 8, 512>>>(feat, out);
}

// round 7
// speedup vs baseline: 2.7424x; 2.7424x over previous
#include <cuda_runtime.h>

#define BB 256
#define NN 400
#define DD 256
#define DEGC 32
#define EE (BB*NN*DEGC)        // 3276800
#define KK 200
#define NCC (NN-KK)            // 200
#define NT (BB*NN)             // 102400
#define BK (BB*KK)             // 51200
#define BC (BB*NCC)            // 51200
#define EG (NN*DEGC)           // 12800 edges per graph
#define EG4 (EG/4)             // 3200

// output offsets (float32 elements)
#define OFF_DIS   ((size_t)0)
#define OFF_COM   ((size_t)BK*DD)                 // 13107200
#define OFF_PERM  (OFF_COM + (size_t)BC*DD)       // 26214400
#define OFF_PERMC (OFF_PERM + BK)                 // 26265600
#define OFF_SOFT  (OFF_PERMC + BC)                // 26316800
#define OFF_EDIS  (OFF_SOFT + NT)                 // 26419200
#define OFF_ECOM  (OFF_EDIS + EE)                 // 29696000

// Deterministic packed accumulator per node (global, L2 atomics):
//   bits [56:64) : deg_in count
//   bits [0:56)  : sum over edges of (llrint((double)h * 2^28) + 2^47)
#define AGG_SCALE 268435456.0           // 2^28
#define AGG_BIAS  (1ll << 47)
#define MASK56    ((1ull << 56) - 1ull)

__device__ unsigned long long g_acc[NT];
__device__ int    g_deg_out[NT];
__device__ float  g_p[NT];         // raw feature @ W
__device__ float  g_h[NT];         // p * deg_out^-1/2
__device__ float  g_score[NT];
__device__ int    g_perm[BK];
__device__ int    g_permc[BC];
__device__ float  g_sumexp;

__device__ __forceinline__ unsigned enc_f(float f) {
    unsigned u = __float_as_uint(f);
    return (u >> 31) ? ~u : (u | 0x80000000u);
}

__global__ void k_init() {
    int i = blockIdx.x * blockDim.x + threadIdx.x;
    if (i < NT) { g_acc[i] = 0ull; g_deg_out[i] = 0; }
    if (i == 0) g_sumexp = 0.f;
}

// Heterogeneous grid: 4-of-5 blocks do p = feat@W (warp per node),
// 1-of-5 blocks do deg_out atomics. grid = 16000 blocks of 256 threads.
__global__ void __launch_bounds__(256) k_xw_deg(const float* __restrict__ feat,
                                                const float* __restrict__ W,
                                                const int* __restrict__ src) {
    int b = blockIdx.x;
    if ((b % 5) == 4) {
        int i = (b / 5) * 256 + threadIdx.x;   // [0, EE/4)
        int4 s = ((const int4*)src)[i];
        atomicAdd(&g_deg_out[s.x], 1); atomicAdd(&g_deg_out[s.y], 1);
        atomicAdd(&g_deg_out[s.z], 1); atomicAdd(&g_deg_out[s.w], 1);
        return;
    }
    __shared__ __align__(16) float sW[DD];
    int t = threadIdx.x;
    for (int i = t; i < DD; i += 256) sW[i] = W[i];
    __syncthreads();
    int chunk = (b / 5) * 4 + (b % 5);         // [0, 12800)
    int warp = t >> 5, lane = t & 31;
    int node = chunk * 8 + warp;
    const float4* f4 = (const float4*)(feat + (size_t)node * DD);
    const float4* w4 = (const float4*)sW;
    float acc = 0.f;
#pragma unroll
    for (int j = 0; j < 2; j++) {
        float4 v = f4[lane * 2 + j];
        float4 w = w4[lane * 2 + j];
        acc += v.x * w.x + v.y * w.y + v.z * w.z + v.w * w.w;
    }
#pragma unroll
    for (int o = 16; o > 0; o >>= 1) acc += __shfl_down_sync(0xffffffffu, acc, o);
    if (lane == 0) g_p[node] = acc;
}

// h = p * deg_out^-1/2 (same arithmetic as before, computed once per node)
__global__ void k_h() {
    int i = blockIdx.x * blockDim.x + threadIdx.x;
    if (i >= NT) return;
    g_h[i] = g_p[i] * rsqrtf(fmaxf((float)g_deg_out[i], 1.f));
}

__device__ __forceinline__ unsigned long long pack_edge(float h) {
    long long fixedv = llrint((double)h * AGG_SCALE);
    return (1ull << 56) + (unsigned long long)(fixedv + AGG_BIAS);
}

// Fused deg_in + agg via one deterministic u64 atomic per edge.
__global__ void __launch_bounds__(256) k_agg(const int* __restrict__ src,
                                             const int* __restrict__ dst) {
    int i = blockIdx.x * blockDim.x + threadIdx.x;
    if (i >= EE / 4) return;
    int4 s = ((const int4*)src)[i];
    int4 d = ((const int4*)dst)[i];
    atomicAdd(&g_acc[d.x], pack_edge(g_h[s.x]));
    atomicAdd(&g_acc[d.y], pack_edge(g_h[s.y]));
    atomicAdd(&g_acc[d.z], pack_edge(g_h[s.z]));
    atomicAdd(&g_acc[d.w], pack_edge(g_h[s.w]));
}

// One block (512 threads) per graph: score + sum-exp + bitonic topk +
// perm/permc writes + edge-mask writes (this graph's contiguous edge range).
__global__ void __launch_bounds__(512) k_topk(const float* __restrict__ bptr,
                                              const int* __restrict__ src,
                                              const int* __restrict__ dst,
                                              float* __restrict__ out) {
    __shared__ unsigned long long keys[512];
    __shared__ int scan[512];
    __shared__ unsigned char flags[512];
    __shared__ float ssc[NN];
    __shared__ float sred[512];
    int g = blockIdx.x;
    int t = threadIdx.x;
    float b0 = bptr[0];

    // decode scores + local exp-sum for this graph's 400 nodes
    float lsum = 0.f;
    if (t < NN) {
        unsigned long long v = g_acc[(size_t)g * NN + t];
        unsigned C = (unsigned)(v >> 56);
        long long S = (long long)(v & MASK56);
        double agg = (double)(S - ((long long)C << 47)) * (1.0 / AGG_SCALE);
        float s = (float)agg * rsqrtf(fmaxf((float)C, 1.f)) + b0;
        ssc[t] = s;
        g_score[(size_t)g * NN + t] = s;
        lsum = expf(s);
    }
    sred[t] = lsum;
    __syncthreads();
    for (int o = 256; o > 0; o >>= 1) {
        if (t < o) sred[t] += sred[t + o];
        __syncthreads();
    }
    if (t == 0) atomicAdd(&g_sumexp, sred[0]);

    // keys: (score desc, idx asc) — one key per thread
    {
        unsigned long long key;
        if (t < NN) {
            unsigned u = enc_f(ssc[t]);
            key = (((unsigned long long)(~u)) << 32) | (unsigned)t;
        } else {
            key = 0xFFFFFFFFFFFFFFFFull;
        }
        keys[t] = key;
        flags[t] = 0;
    }
    __syncthreads();
    for (int k = 2; k <= 512; k <<= 1) {
        for (int j = k >> 1; j > 0; j >>= 1) {
            int ixj = t ^ j;
            if (ixj > t) {
                bool up = ((t & k) == 0);
                unsigned long long a = keys[t], c = keys[ixj];
                if ((a > c) == up) { keys[t] = c; keys[ixj] = a; }
            }
            __syncthreads();
        }
    }
    if (t < KK) {
        int local = (int)(keys[t] & 0xffffffffu);
        flags[local] = 1;
        int gid = g * NN + local;
        g_perm[g * KK + t] = gid;
        out[OFF_PERM + (size_t)g * KK + t] = (float)gid;
    }
    __syncthreads();
    scan[t] = (t < NN && !flags[t]) ? 1 : 0;
    __syncthreads();
    for (int off = 1; off < 512; off <<= 1) {
        int add = (t >= off) ? scan[t - off] : 0;
        __syncthreads();
        scan[t] += add;
        __syncthreads();
    }
    if (t < NN && !flags[t]) {
        int p = scan[t] - 1;
        int gid = g * NN + t;
        g_permc[g * NCC + p] = gid;
        out[OFF_PERMC + (size_t)g * NCC + p] = (float)gid;
    }
    __syncthreads();

    // edge masks for this graph's contiguous edge range (streaming loads)
    const int4* s4 = (const int4*)src + (size_t)g * EG4;
    const int4* d4 = (const int4*)dst + (size_t)g * EG4;
    float4* odis = (float4*)(out + OFF_EDIS) + (size_t)g * EG4;
    float4* ocom = (float4*)(out + OFF_ECOM) + (size_t)g * EG4;
    int base = g * NN;
    for (int i = t; i < EG4; i += 512) {
        int4 s = __ldcs(&s4[i]);
        int4 d = __ldcs(&d4[i]);
        unsigned char sx = flags[s.x - base], sy = flags[s.y - base];
        unsigned char sz = flags[s.z - base], sw = flags[s.w - base];
        unsigned char dx = flags[d.x - base], dy = flags[d.y - base];
        unsigned char dz = flags[d.z - base], dw = flags[d.w - base];
        float4 dis, com;
        dis.x = (sx & dx) ? 1.f : 0.f;  com.x = (!sx && !dx) ? 1.f : 0.f;
        dis.y = (sy & dy) ? 1.f : 0.f;  com.y = (!sy && !dy) ? 1.f : 0.f;
        dis.z = (sz & dz) ? 1.f : 0.f;  com.z = (!sz && !dz) ? 1.f : 0.f;
        dis.w = (sw & dw) ? 1.f : 0.f;  com.w = (!sw && !dw) ? 1.f : 0.f;
        __stcs(&odis[i], dis);
        __stcs(&ocom[i], com);
    }
}

// Gather + softmax. 512 threads = 16 rows x 32 lanes, 2 float4s per thread
// (MLP=2). Streaming loads/stores: each feature row is read exactly once here,
// outputs never re-read.
__global__ void __launch_bounds__(512) k_gather(const float* __restrict__ feat,
                                                float* __restrict__ out) {
    int t = threadIdx.x;
    int rowInBlk = t >> 5;        // 16 rows per block
    int lane = t & 31;
    long row = (long)blockIdx.x * 16 + rowInBlk;
    int node; size_t obase;
    if (row < BK) {
        node = g_perm[row];
        obase = OFF_DIS + (size_t)row * DD;
    } else {
        long r2 = row - BK;
        node = g_permc[r2];
        obase = OFF_COM + (size_t)r2 * DD;
    }
    float sc = g_score[node];
    float gate = tanhf(sc);
    const float4* f4 = (const float4*)(feat + (size_t)node * DD);
    float4* o4 = (float4*)(out + obase);
    float4 v0 = __ldcs(&f4[lane]);
    float4 v1 = __ldcs(&f4[lane + 32]);
    v0.x *= gate; v0.y *= gate; v0.z *= gate; v0.w *= gate;
    v1.x *= gate; v1.y *= gate; v1.z *= gate; v1.w *= gate;
    __stcs(&o4[lane], v0);
    __stcs(&o4[lane + 32], v1);
    if (lane == 0) out[OFF_SOFT + node] = expf(sc) / g_sumexp;
}

extern "C" void kernel_launch(void* const* d_in, const int* in_sizes, int n_in,
                              void* d_out, int out_size) {
    const float* feat = (const float*)d_in[0];
    const float* W    = (const float*)d_in[1];
    const float* b    = (const float*)d_in[2];
    const int*   src  = (const int*)d_in[3];
    const int*   dst  = (const int*)d_in[4];
    float* out = (float*)d_out;
    (void)in_sizes; (void)n_in; (void)out_size;

    k_init<<<(NT + 255) / 256, 256>>>();
    k_xw_deg<<<16000, 256>>>(feat, W, src);
    k_h<<<NT / 256, 256>>>();
    k_agg<<<(EE / 4 + 255) / 256, 256>>>(src, dst);
    k_topk<<<BB, 512>>>(b, src, dst, out);
    k_gather<<<NT / 16, 512>>>(feat, out);
}